// round 1
// baseline (speedup 1.0000x reference)
#include <cuda_runtime.h>
#include <math.h>

#define C_     128
#define BATCH  2
#define S_     110592          // 48*48*48
#define NPTS   221184          // BATCH*S_
#define CH     512

// ---------------- scratch (static __device__ allowed) ----------------
__device__ float g_yconv[(size_t)BATCH * C_ * S_];     // conv out, NCDHW   (113MB)
__device__ float g_ylnt [(size_t)BATCH * C_ * S_];     // LN out, panel [panel][c][128] (113MB)
__device__ float g_h    [(size_t)NPTS * CH];           // gelu out, panel [panel][e][128] (453MB)
__device__ float g_gsq  [BATCH * CH];
__device__ float g_s    [BATCH * CH];
__device__ float g_bias2[C_];

// ---------------- K0: zero gsq ----------------
__global__ void zero_gsq_kernel() {
    int i = threadIdx.x;
    if (i < BATCH * CH) g_gsq[i] = 0.f;
}

// ---------------- K1: depthwise 7x7x7 conv, NCDHW, smem plane ring ----------------
// grid (4 dchunks, 128 c, 2 b), 192 threads, dynamic smem = (7*2916 + 343 + 2304)*4
__global__ void conv_dw_kernel(const float* __restrict__ x, const float* __restrict__ dw_w) {
    extern __shared__ float sm[];
    float* planes = sm;                 // 7 * 54*54
    float* wsm    = sm + 7 * 2916;      // 343
    float* outsm  = wsm + 343;          // 48*48

    const int tid = threadIdx.x;        // 0..191
    const int dstart = blockIdx.x * 12;
    const int c = blockIdx.y;
    const int b = blockIdx.z;
    const size_t xbase = ((size_t)(b * C_ + c)) * S_;

    for (int i = tid; i < 343; i += 192) wsm[i] = dw_w[c * 343 + i];

    // preload 7 halo planes: din = dstart-3 .. dstart+3
    for (int pl = 0; pl < 7; ++pl) {
        int din = dstart - 3 + pl;
        int slot = ((din % 7) + 7) % 7;
        float* dst = planes + slot * 2916;
        if (din < 0 || din >= 48) {
            for (int i = tid; i < 2916; i += 192) dst[i] = 0.f;
        } else {
            const float* src = x + xbase + (size_t)din * 2304;
            for (int i = tid; i < 2916; i += 192) {
                int hh = i / 54 - 3, ww = i % 54 - 3;
                dst[i] = (hh >= 0 && hh < 48 && ww >= 0 && ww < 48) ? src[hh * 48 + ww] : 0.f;
            }
        }
    }

    const int tx = tid & 7, ty = tid >> 3;      // tx 0..7, ty 0..23
    const int w0 = tx * 6, h0 = ty * 2;

    for (int d = dstart; d < dstart + 12; ++d) {
        __syncthreads();                         // planes ready
        float acc[2][6];
        #pragma unroll
        for (int r = 0; r < 2; ++r)
            #pragma unroll
            for (int j = 0; j < 6; ++j) acc[r][j] = 0.f;

        #pragma unroll 1
        for (int dd = 0; dd < 7; ++dd) {
            const float* pl = planes + (((d - 3 + dd) % 7 + 7) % 7) * 2916;
            #pragma unroll
            for (int dh = 0; dh < 7; ++dh) {
                float wv[7];
                #pragma unroll
                for (int k = 0; k < 7; ++k) wv[k] = wsm[dd * 49 + dh * 7 + k];
                #pragma unroll
                for (int r = 0; r < 2; ++r) {
                    const float* row = pl + (h0 + r + dh) * 54 + w0;
                    float xr[12];
                    #pragma unroll
                    for (int q = 0; q < 12; ++q) xr[q] = row[q];
                    #pragma unroll
                    for (int j = 0; j < 6; ++j)
                        #pragma unroll
                        for (int k = 0; k < 7; ++k)
                            acc[r][j] = fmaf(xr[j + k], wv[k], acc[r][j]);
                }
            }
        }
        #pragma unroll
        for (int r = 0; r < 2; ++r)
            #pragma unroll
            for (int j = 0; j < 6; ++j)
                outsm[(h0 + r) * 48 + w0 + j] = acc[r][j];
        __syncthreads();                         // outsm ready, planes free
        float* dst = g_yconv + xbase + (size_t)d * 2304;
        for (int i = tid; i < 2304; i += 192) dst[i] = outsm[i];
        if (d + 1 < dstart + 12) {
            int din = d + 4;
            int slot = ((din % 7) + 7) % 7;
            float* dstp = planes + slot * 2916;
            if (din >= 48) {
                for (int i = tid; i < 2916; i += 192) dstp[i] = 0.f;
            } else {
                const float* src = x + xbase + (size_t)din * 2304;
                for (int i = tid; i < 2916; i += 192) {
                    int hh = i / 54 - 3, ww = i % 54 - 3;
                    dstp[i] = (hh >= 0 && hh < 48 && ww >= 0 && ww < 48) ? src[hh * 48 + ww] : 0.f;
                }
            }
        }
    }
}

// ---------------- K2: transpose + dw_b + LayerNorm -> panel layout ----------------
// grid (S_/32, B), 256 threads (32 x 8)
__global__ void trans_ln_kernel(const float* __restrict__ dwb,
                                const float* __restrict__ lng,
                                const float* __restrict__ lnb) {
    __shared__ float tile[C_ * 33];
    __shared__ float ps[256], pq[256], musm[32], rssm[32];
    const int tid = threadIdx.x;
    const int tx = tid & 31, ty = tid >> 5;
    const int p0 = blockIdx.x * 32;
    const int b = blockIdx.y;

    for (int g = 0; g < 16; ++g) {
        int c = ty * 16 + g;
        tile[c * 33 + tx] = g_yconv[((size_t)(b * C_ + c)) * S_ + p0 + tx] + dwb[c];
    }
    __syncthreads();
    float s = 0.f, q = 0.f;
    for (int g = 0; g < 16; ++g) {
        float v = tile[(ty * 16 + g) * 33 + tx];
        s += v; q += v * v;
    }
    ps[ty * 32 + tx] = s; pq[ty * 32 + tx] = q;
    __syncthreads();
    if (ty == 0) {
        float S1 = 0.f, Q1 = 0.f;
        for (int u = 0; u < 8; ++u) { S1 += ps[u * 32 + tx]; Q1 += pq[u * 32 + tx]; }
        float mu = S1 * (1.f / 128.f);
        float var = Q1 * (1.f / 128.f) - mu * mu;
        musm[tx] = mu;
        rssm[tx] = rsqrtf(var + 1e-6f);
    }
    __syncthreads();
    size_t panel = ((size_t)b * S_ + p0) >> 7;
    int mo = (int)(((size_t)b * S_ + p0) & 127);
    float* dst = g_ylnt + panel * 16384 + mo;
    for (int t = 0; t < 16; ++t) {
        int idx = tid + 256 * t;
        int p = idx & 31, c = idx >> 5;
        float v = (tile[c * 33 + p] - musm[p]) * rssm[p] * lng[c] + lnb[c];
        dst[c * 128 + p] = v;
    }
}

// ---------------- K3: GEMM1 (yln @ w1) + b1 + exact GELU -> h (panel), + gsq atomics ----
// grid (NPTS/128, CH/128), 256 threads, dynamic smem 131072
__global__ void gemm1_kernel(const float* __restrict__ w1, const float* __restrict__ b1) {
    extern __shared__ float smem[];
    float* As = smem;            // [k][m] 128x128
    float* Bs = smem + 16384;    // [k][n] 128x128
    const int tid = threadIdx.x;
    const int bx = blockIdx.x, bn = blockIdx.y;
    const int n0 = bn * 128;

    float4* As4 = (float4*)As;
    float4* Bs4 = (float4*)Bs;
    const float4* Ag = (const float4*)(g_ylnt + (size_t)bx * 16384);
    const float4* Bg = (const float4*)w1;      // w1 row = 512 floats = 128 float4

    #pragma unroll
    for (int j = 0; j < 16; ++j) {
        int idx = tid + 256 * j;
        As4[idx] = Ag[idx];
        int k = idx >> 5, nf = idx & 31;
        Bs4[idx] = Bg[k * 128 + (n0 >> 2) + nf];
    }
    __syncthreads();

    const int cth = tid & 15, rth = tid >> 4;   // m-tile = cth*8.., n-tile = rth*8..
    float acc[8][8];
    #pragma unroll
    for (int i = 0; i < 8; ++i)
        #pragma unroll
        for (int j = 0; j < 8; ++j) acc[i][j] = 0.f;

    #pragma unroll 4
    for (int k = 0; k < 128; ++k) {
        float4 a0 = As4[k * 32 + cth * 2];
        float4 a1 = As4[k * 32 + cth * 2 + 1];
        float4 b0 = Bs4[k * 32 + rth * 2];
        float4 b1v = Bs4[k * 32 + rth * 2 + 1];
        float a[8] = {a0.x, a0.y, a0.z, a0.w, a1.x, a1.y, a1.z, a1.w};
        float bb[8] = {b0.x, b0.y, b0.z, b0.w, b1v.x, b1v.y, b1v.z, b1v.w};
        #pragma unroll
        for (int i = 0; i < 8; ++i)
            #pragma unroll
            for (int j = 0; j < 8; ++j)
                acc[i][j] = fmaf(a[i], bb[j], acc[i][j]);
    }

    const int bloc = (bx * 128) / S_;
    float* Hp = g_h + (size_t)bx * 65536;
    float sq[8];
    #pragma unroll
    for (int j = 0; j < 8; ++j) sq[j] = 0.f;

    #pragma unroll
    for (int j = 0; j < 8; ++j) {
        int e = n0 + rth * 8 + j;
        float bv = b1[e];
        float tmp[8];
        #pragma unroll
        for (int i = 0; i < 8; ++i) {
            float v = acc[i][j] + bv;
            float gl = 0.5f * v * (1.0f + erff(v * 0.70710678118654752f));
            tmp[i] = gl;
            sq[j] += gl * gl;
        }
        float4* dst = (float4*)(Hp + (size_t)e * 128 + cth * 8);
        dst[0] = make_float4(tmp[0], tmp[1], tmp[2], tmp[3]);
        dst[1] = make_float4(tmp[4], tmp[5], tmp[6], tmp[7]);
    }
    // reduce partial squared sums over the 16 lanes sharing the same n-tile
    #pragma unroll
    for (int j = 0; j < 8; ++j) {
        float v = sq[j];
        #pragma unroll
        for (int o = 8; o >= 1; o >>= 1) v += __shfl_xor_sync(0xffffffffu, v, o);
        if ((tid & 15) == 0) atomicAdd(&g_gsq[bloc * CH + n0 + rth * 8 + j], v);
    }
}

// ---------------- K4: GRN scale s[b][e] and bias2[c] = b2 + grn_b @ w2 ----------------
__global__ void grn_prep_kernel(const float* __restrict__ grn_g, const float* __restrict__ grn_b,
                                const float* __restrict__ w2, const float* __restrict__ b2) {
    if (blockIdx.x == 0) {
        __shared__ float red[512];
        int e = threadIdx.x;
        for (int b = 0; b < BATCH; ++b) {
            float g = sqrtf(g_gsq[b * CH + e]);
            red[e] = g;
            __syncthreads();
            for (int o = 256; o > 0; o >>= 1) {
                if (e < o) red[e] += red[e + o];
                __syncthreads();
            }
            float mean = red[0] * (1.f / 512.f);
            __syncthreads();
            float nx = g / (mean + 1e-6f);
            g_s[b * CH + e] = 1.f + grn_g[e] * nx;
        }
    } else {
        int c = threadIdx.x;
        if (c < C_) {
            float a = b2[c];
            for (int e = 0; e < CH; ++e) a += grn_b[e] * w2[e * C_ + c];
            g_bias2[c] = a;
        }
    }
}

// ---------------- K5: GEMM2 ((h*s) @ w2) + bias2 + residual -> out NCDHW ----------------
// grid (NPTS/128), 256 threads, dynamic smem 131072
__global__ void gemm2_kernel(const float* __restrict__ w2, const float* __restrict__ xin,
                             float* __restrict__ out) {
    extern __shared__ float smem[];
    float* As = smem;
    float* Bs = smem + 16384;
    const int tid = threadIdx.x;
    const int bx = blockIdx.x;
    const int bloc = (bx * 128) / S_;
    const int cth = tid & 15, rth = tid >> 4;

    float4* As4 = (float4*)As;
    float4* Bs4 = (float4*)Bs;
    const float4* Bg = (const float4*)w2;      // w2 row = 128 floats = 32 float4

    float acc[8][8];
    #pragma unroll
    for (int i = 0; i < 8; ++i)
        #pragma unroll
        for (int j = 0; j < 8; ++j) acc[i][j] = 0.f;

    for (int kc = 0; kc < 4; ++kc) {
        const float4* Ag = (const float4*)(g_h + (size_t)bx * 65536 + kc * 16384);
        const float* sp = g_s + bloc * CH + kc * 128;
        #pragma unroll
        for (int j = 0; j < 16; ++j) {
            int idx = tid + 256 * j;
            int k = idx >> 5;
            float sv = sp[k];
            float4 v = Ag[idx];
            v.x *= sv; v.y *= sv; v.z *= sv; v.w *= sv;
            As4[idx] = v;
            Bs4[idx] = Bg[(kc * 128 + k) * 32 + (idx & 31)];
        }
        __syncthreads();
        #pragma unroll 4
        for (int k = 0; k < 128; ++k) {
            float4 a0 = As4[k * 32 + cth * 2];
            float4 a1 = As4[k * 32 + cth * 2 + 1];
            float4 b0 = Bs4[k * 32 + rth * 2];
            float4 b1v = Bs4[k * 32 + rth * 2 + 1];
            float a[8] = {a0.x, a0.y, a0.z, a0.w, a1.x, a1.y, a1.z, a1.w};
            float bb[8] = {b0.x, b0.y, b0.z, b0.w, b1v.x, b1v.y, b1v.z, b1v.w};
            #pragma unroll
            for (int i = 0; i < 8; ++i)
                #pragma unroll
                for (int j = 0; j < 8; ++j)
                    acc[i][j] = fmaf(a[i], bb[j], acc[i][j]);
        }
        __syncthreads();
    }

    // epilogue: stage to smem (overlays As/Bs; safe after sync), then coalesced NCDHW write
    float* Cs = smem;        // [m][c] with row length 131 (conflict-free read)
    #pragma unroll
    for (int j = 0; j < 8; ++j) {
        float bv = g_bias2[rth * 8 + j];
        #pragma unroll
        for (int i = 0; i < 8; ++i)
            Cs[(cth * 8 + i) * 131 + rth * 8 + j] = acc[i][j] + bv;
    }
    __syncthreads();
    const int P0 = (bx * 128) % S_;
    for (int t = 0; t < 64; ++t) {
        int idx = tid + 256 * t;
        int p = idx & 127, cc = idx >> 7;
        size_t go = ((size_t)(bloc * C_ + cc)) * S_ + P0 + p;
        out[go] = xin[go] + Cs[p * 131 + cc];
    }
}

// ---------------- launch ----------------
extern "C" void kernel_launch(void* const* d_in, const int* in_sizes, int n_in,
                              void* d_out, int out_size) {
    (void)in_sizes; (void)n_in; (void)out_size;
    const float* x     = (const float*)d_in[0];
    const float* dw_w  = (const float*)d_in[1];
    const float* dw_b  = (const float*)d_in[2];
    const float* ln_g  = (const float*)d_in[3];
    const float* ln_b  = (const float*)d_in[4];
    const float* w1    = (const float*)d_in[5];
    const float* b1    = (const float*)d_in[6];
    const float* grn_g = (const float*)d_in[7];
    const float* grn_b = (const float*)d_in[8];
    const float* w2    = (const float*)d_in[9];
    const float* b2    = (const float*)d_in[10];
    float* out = (float*)d_out;

    const int conv_smem = (7 * 2916 + 343 + 2304) * 4;   // 92236
    const int gemm_smem = 32768 * 4;                     // 131072
    cudaFuncSetAttribute(conv_dw_kernel, cudaFuncAttributeMaxDynamicSharedMemorySize, conv_smem);
    cudaFuncSetAttribute(gemm1_kernel,  cudaFuncAttributeMaxDynamicSharedMemorySize, gemm_smem);
    cudaFuncSetAttribute(gemm2_kernel,  cudaFuncAttributeMaxDynamicSharedMemorySize, gemm_smem);

    zero_gsq_kernel<<<1, 1024>>>();
    conv_dw_kernel<<<dim3(4, C_, BATCH), 192, conv_smem>>>(x, dw_w);
    trans_ln_kernel<<<dim3(S_ / 32, BATCH), 256>>>(dw_b, ln_g, ln_b);
    gemm1_kernel<<<dim3(NPTS / 128, CH / 128), 256, gemm_smem>>>(w1, b1);
    grn_prep_kernel<<<2, 512>>>(grn_g, grn_b, w2, b2);
    gemm2_kernel<<<NPTS / 128, 256, gemm_smem>>>(w2, x, out);
}

// round 4
// speedup vs baseline: 1.3832x; 1.3832x over previous
#include <cuda_runtime.h>
#include <cuda_bf16.h>
#include <math.h>
#include <stdint.h>

#define C_     128
#define BATCH  2
#define S_     110592          // 48*48*48
#define NPTS   221184
#define CH     512
#define NPANEL 1728            // NPTS/128
#define PPB    864             // panels per batch

typedef unsigned int uint;
typedef unsigned short ushort;

// single extern shared decl shared by all kernels
extern __shared__ __align__(128) unsigned char smraw[];

// ---------------- scratch ----------------
__device__ float  g_yconv[(size_t)BATCH * C_ * S_];     // conv out NCDHW
__device__ ushort g_ylnh[(size_t)NPTS * C_];            // LN out hi bf16, [panel][m][k]
__device__ ushort g_ylnl[(size_t)NPTS * C_];            // LN out lo
__device__ ushort g_hh  [(size_t)NPTS * CH];            // gelu out hi, [panel][m][e]
__device__ ushort g_hl  [(size_t)NPTS * CH];            // gelu out lo
__device__ ushort g_w1h [CH * C_];                      // w1^T hi: [e][c]
__device__ ushort g_w1l [CH * C_];
__device__ ushort g_w2h [BATCH * C_ * CH];              // scaled w2^T hi: [b][c][e]
__device__ ushort g_w2l [BATCH * C_ * CH];
__device__ float  g_gsq [BATCH * CH];
__device__ float  g_s   [BATCH * CH];
__device__ float  g_bias2[C_];

// ---------------- PTX helpers ----------------
__device__ __forceinline__ uint32_t smem_u32(const void* p) {
    uint32_t a;
    asm("{ .reg .u64 t; cvta.to.shared.u64 t, %1; cvt.u32.u64 %0, t; }" : "=r"(a) : "l"(p));
    return a;
}
#define CP_ASYNC(dst, src) asm volatile("cp.async.cg.shared.global [%0], [%1], 16;" :: "r"(dst), "l"(src))
#define CP_COMMIT()        asm volatile("cp.async.commit_group;")
#define CP_WAIT1()         asm volatile("cp.async.wait_group 1;")
#define CP_WAIT0()         asm volatile("cp.async.wait_group 0;")

__device__ __forceinline__ void ldsm4(uint* r, uint32_t addr) {
    asm volatile("ldmatrix.sync.aligned.m8n8.x4.shared.b16 {%0,%1,%2,%3}, [%4];"
        : "=r"(r[0]), "=r"(r[1]), "=r"(r[2]), "=r"(r[3]) : "r"(addr));
}
__device__ __forceinline__ void mma_bf16(float* c, const uint* a, uint b0, uint b1) {
    asm volatile("mma.sync.aligned.m16n8k16.row.col.f32.bf16.bf16.f32 "
        "{%0,%1,%2,%3}, {%4,%5,%6,%7}, {%8,%9}, {%0,%1,%2,%3};"
        : "+f"(c[0]), "+f"(c[1]), "+f"(c[2]), "+f"(c[3])
        : "r"(a[0]), "r"(a[1]), "r"(a[2]), "r"(a[3]), "r"(b0), "r"(b1));
}
__device__ __forceinline__ void split2(float a, float b, uint& hi, uint& lo) {
    __nv_bfloat16 ah = __float2bfloat16_rn(a), bh = __float2bfloat16_rn(b);
    float ar = a - __bfloat162float(ah), br = b - __bfloat162float(bh);
    __nv_bfloat16 al = __float2bfloat16_rn(ar), bl = __float2bfloat16_rn(br);
    hi = ((uint)__bfloat16_as_ushort(bh) << 16) | (uint)__bfloat16_as_ushort(ah);
    lo = ((uint)__bfloat16_as_ushort(bl) << 16) | (uint)__bfloat16_as_ushort(al);
}
__device__ __forceinline__ float gelu_f(float v) {
    return 0.5f * v * (1.0f + erff(v * 0.70710678118654752f));
}

// shared-memory tile layout per stage (16KB): planes Ah@0, Al@4096, Bh@8192, Bl@12288
// each plane: 128 rows x 16 bf16 (32B/row, two 16B chunks), chunk swizzle: phys_c = c ^ ((r>>2)&1)

__device__ __forceinline__ void gemm_load_stage(uint32_t sdst,
    const char* gAh, const char* gAl, const char* gBh, const char* gBl) {
    CP_ASYNC(sdst         , gAh);
    CP_ASYNC(sdst +  4096u, gAl);
    CP_ASYNC(sdst +  8192u, gBh);
    CP_ASYNC(sdst + 12288u, gBl);
    CP_COMMIT();
}

__device__ __forceinline__ void gemm_compute_stage(uint32_t sa,
    int ar, int asw, int br, int bsw, float acc[4][4][4]) {
    uint aH[4][4], aL[4][4], bH[2][4], bL[2][4];
    uint32_t abase = sa + (uint32_t)(ar * 32 + asw * 16);
    #pragma unroll
    for (int i = 0; i < 4; ++i) ldsm4(aH[i], abase + i * 512u);
    #pragma unroll
    for (int i = 0; i < 4; ++i) ldsm4(aL[i], abase + 4096u + i * 512u);
    uint32_t bbase = sa + 8192u + (uint32_t)(br * 32 + bsw * 16);
    #pragma unroll
    for (int j = 0; j < 2; ++j) ldsm4(bH[j], bbase + j * 512u);
    #pragma unroll
    for (int j = 0; j < 2; ++j) ldsm4(bL[j], bbase + 4096u + j * 512u);
    #pragma unroll
    for (int i = 0; i < 4; ++i)
        #pragma unroll
        for (int j = 0; j < 4; ++j) {
            uint h0 = bH[j >> 1][(j & 1) * 2], h1 = bH[j >> 1][(j & 1) * 2 + 1];
            uint l0 = bL[j >> 1][(j & 1) * 2], l1 = bL[j >> 1][(j & 1) * 2 + 1];
            mma_bf16(acc[i][j], aH[i], h0, h1);
            mma_bf16(acc[i][j], aH[i], l0, l1);
            mma_bf16(acc[i][j], aL[i], h0, h1);
        }
}

// ---------------- K0: zero gsq ----------------
__global__ void zero_gsq_kernel() {
    int i = threadIdx.x;
    if (i < BATCH * CH) g_gsq[i] = 0.f;
}

// ---------------- K1: depthwise 7x7x7 conv ----------------
__global__ void conv_dw_kernel(const float* __restrict__ x, const float* __restrict__ dw_w) {
    float* sm = (float*)smraw;
    float* planes = sm;
    float* wsm    = sm + 7 * 2916;
    float* outsm  = wsm + 343;

    const int tid = threadIdx.x;
    const int dstart = blockIdx.x * 12;
    const int c = blockIdx.y;
    const int b = blockIdx.z;
    const size_t xbase = ((size_t)(b * C_ + c)) * S_;

    for (int i = tid; i < 343; i += 192) wsm[i] = dw_w[c * 343 + i];

    for (int pl = 0; pl < 7; ++pl) {
        int din = dstart - 3 + pl;
        int slot = ((din % 7) + 7) % 7;
        float* dst = planes + slot * 2916;
        if (din < 0 || din >= 48) {
            for (int i = tid; i < 2916; i += 192) dst[i] = 0.f;
        } else {
            const float* src = x + xbase + (size_t)din * 2304;
            for (int i = tid; i < 2916; i += 192) {
                int hh = i / 54 - 3, ww = i % 54 - 3;
                dst[i] = (hh >= 0 && hh < 48 && ww >= 0 && ww < 48) ? src[hh * 48 + ww] : 0.f;
            }
        }
    }

    const int tx = tid & 7, ty = tid >> 3;
    const int w0 = tx * 6, h0 = ty * 2;

    for (int d = dstart; d < dstart + 12; ++d) {
        __syncthreads();
        float acc[2][6];
        #pragma unroll
        for (int r = 0; r < 2; ++r)
            #pragma unroll
            for (int j = 0; j < 6; ++j) acc[r][j] = 0.f;

        #pragma unroll 1
        for (int dd = 0; dd < 7; ++dd) {
            const float* pl = planes + (((d - 3 + dd) % 7 + 7) % 7) * 2916;
            #pragma unroll
            for (int dh = 0; dh < 7; ++dh) {
                float wv[7];
                #pragma unroll
                for (int k = 0; k < 7; ++k) wv[k] = wsm[dd * 49 + dh * 7 + k];
                #pragma unroll
                for (int r = 0; r < 2; ++r) {
                    const float* row = pl + (h0 + r + dh) * 54 + w0;
                    float xr[12];
                    #pragma unroll
                    for (int q = 0; q < 12; ++q) xr[q] = row[q];
                    #pragma unroll
                    for (int j = 0; j < 6; ++j)
                        #pragma unroll
                        for (int k = 0; k < 7; ++k)
                            acc[r][j] = fmaf(xr[j + k], wv[k], acc[r][j]);
                }
            }
        }
        #pragma unroll
        for (int r = 0; r < 2; ++r)
            #pragma unroll
            for (int j = 0; j < 6; ++j)
                outsm[(h0 + r) * 48 + w0 + j] = acc[r][j];
        __syncthreads();
        float* dst = g_yconv + xbase + (size_t)d * 2304;
        for (int i = tid; i < 2304; i += 192) dst[i] = outsm[i];
        if (d + 1 < dstart + 12) {
            int din = d + 4;
            int slot = ((din % 7) + 7) % 7;
            float* dstp = planes + slot * 2916;
            if (din >= 48) {
                for (int i = tid; i < 2916; i += 192) dstp[i] = 0.f;
            } else {
                const float* src = x + xbase + (size_t)din * 2304;
                for (int i = tid; i < 2916; i += 192) {
                    int hh = i / 54 - 3, ww = i % 54 - 3;
                    dstp[i] = (hh >= 0 && hh < 48 && ww >= 0 && ww < 48) ? src[hh * 48 + ww] : 0.f;
                }
            }
        }
    }
}

// ---------------- K2: transpose + dw_b + LN -> split bf16 [panel][m][k] ----------------
__global__ void trans_ln_kernel(const float* __restrict__ dwb,
                                const float* __restrict__ lng,
                                const float* __restrict__ lnb) {
    __shared__ float tile[C_ * 33];
    __shared__ float ps[256], pq[256], musm[32], rssm[32];
    const int tid = threadIdx.x;
    const int tx = tid & 31, ty = tid >> 5;
    const int p0 = blockIdx.x * 32;
    const int b = blockIdx.y;

    for (int g = 0; g < 16; ++g) {
        int c = ty * 16 + g;
        tile[c * 33 + tx] = g_yconv[((size_t)(b * C_ + c)) * S_ + p0 + tx] + dwb[c];
    }
    __syncthreads();
    float s = 0.f, q = 0.f;
    for (int g = 0; g < 16; ++g) {
        float v = tile[(ty * 16 + g) * 33 + tx];
        s += v; q += v * v;
    }
    ps[ty * 32 + tx] = s; pq[ty * 32 + tx] = q;
    __syncthreads();
    if (ty == 0) {
        float S1 = 0.f, Q1 = 0.f;
        for (int u = 0; u < 8; ++u) { S1 += ps[u * 32 + tx]; Q1 += pq[u * 32 + tx]; }
        float mu = S1 * (1.f / 128.f);
        float var = Q1 * (1.f / 128.f) - mu * mu;
        musm[tx] = mu;
        rssm[tx] = rsqrtf(var + 1e-6f);
    }
    __syncthreads();
    size_t panel = ((size_t)b * S_ + p0) >> 7;
    int mo = (int)(((size_t)b * S_ + p0) & 127);
    ushort* dh = g_ylnh + panel * 16384;
    ushort* dl = g_ylnl + panel * 16384;
    for (int t = 0; t < 16; ++t) {
        int idx = tid + 256 * t;
        int c = idx & 127, pp = idx >> 7;           // pp 0..31
        float v = (tile[c * 33 + pp] - musm[pp]) * rssm[pp] * lng[c] + lnb[c];
        __nv_bfloat16 h = __float2bfloat16_rn(v);
        float rem = v - __bfloat162float(h);
        dh[(mo + pp) * 128 + c] = __bfloat16_as_ushort(h);
        dl[(mo + pp) * 128 + c] = __bfloat16_as_ushort(__float2bfloat16_rn(rem));
    }
}

// ---------------- K2b: w1 -> transposed split bf16 planes [e][c] ----------------
__global__ void w1cvt_kernel(const float* __restrict__ w1) {
    int id = blockIdx.x * 512 + threadIdx.x;       // 65536 elems
    int cc = id >> 9, e = id & 511;                // w1[cc][e]
    float v = w1[id];
    __nv_bfloat16 h = __float2bfloat16_rn(v);
    float rem = v - __bfloat162float(h);
    g_w1h[e * 128 + cc] = __bfloat16_as_ushort(h);
    g_w1l[e * 128 + cc] = __bfloat16_as_ushort(__float2bfloat16_rn(rem));
}

// ---------------- K3: GEMM1 (HMMA split-bf16) + b1 + GELU -> h planes, + gsq ----------------
// grid (4, NPANEL), 256 threads, smem 32768
__global__ void __launch_bounds__(256) gemm1_mma(const float* __restrict__ b1) {
    const int tid = threadIdx.x;
    const int n0 = blockIdx.x * 128;
    const int bx = blockIdx.y;
    const uint32_t smb = smem_u32(smraw);

    const int r = tid >> 1, cc = tid & 1;
    const int csw = (cc ^ ((r >> 2) & 1)) & 1;
    const uint32_t sdst0 = smb + (uint32_t)(r * 32 + csw * 16);
    const char* gAh = (const char*)(g_ylnh + (size_t)bx * 16384 + r * 128 + cc * 8);
    const char* gAl = (const char*)(g_ylnl + (size_t)bx * 16384 + r * 128 + cc * 8);
    const char* gBh = (const char*)(g_w1h + (size_t)(n0 + r) * 128 + cc * 8);
    const char* gBl = (const char*)(g_w1l + (size_t)(n0 + r) * 128 + cc * 8);

    const int L = tid & 31, wid = tid >> 5, wm = wid & 1, wn = wid >> 1;
    const int ar = wm * 64 + ((L & 7) | (((L >> 3) & 1) << 3));
    const int asw = (((L >> 4) & 1) ^ ((ar >> 2) & 1)) & 1;
    const int br = wn * 32 + ((L & 7) | (((L >> 4) & 1) << 3));
    const int bsw = (((L >> 3) & 1) ^ ((br >> 2) & 1)) & 1;

    float acc[4][4][4];
    #pragma unroll
    for (int i = 0; i < 4; ++i)
        #pragma unroll
        for (int j = 0; j < 4; ++j)
            #pragma unroll
            for (int k = 0; k < 4; ++k) acc[i][j][k] = 0.f;

    const int NK = 8;   // K=128
    gemm_load_stage(sdst0, gAh, gAl, gBh, gBl);
    for (int s = 0; s < NK; ++s) {
        if (s + 1 < NK) {
            gemm_load_stage(sdst0 + (uint32_t)((s + 1) & 1) * 16384u,
                            gAh + (s + 1) * 32, gAl + (s + 1) * 32,
                            gBh + (s + 1) * 32, gBl + (s + 1) * 32);
            CP_WAIT1();
        } else CP_WAIT0();
        __syncthreads();
        gemm_compute_stage(smb + (uint32_t)(s & 1) * 16384u, ar, asw, br, bsw, acc);
        __syncthreads();
    }

    // epilogue
    const int bloc = (bx >= PPB) ? 1 : 0;
    ushort* hh = g_hh + (size_t)bx * 65536;
    ushort* hl = g_hl + (size_t)bx * 65536;
    float sqa[4][2];
    #pragma unroll
    for (int j = 0; j < 4; ++j) { sqa[j][0] = 0.f; sqa[j][1] = 0.f; }

    #pragma unroll
    for (int i = 0; i < 4; ++i) {
        const int m = wm * 64 + i * 16 + (L >> 2);
        #pragma unroll
        for (int j = 0; j < 4; ++j) {
            const int n = n0 + wn * 32 + j * 8 + (L & 3) * 2;
            float b10 = __ldg(b1 + n), b11 = __ldg(b1 + n + 1);
            float v00 = gelu_f(acc[i][j][0] + b10);
            float v01 = gelu_f(acc[i][j][1] + b11);
            float v10 = gelu_f(acc[i][j][2] + b10);
            float v11 = gelu_f(acc[i][j][3] + b11);
            sqa[j][0] += v00 * v00 + v10 * v10;
            sqa[j][1] += v01 * v01 + v11 * v11;
            uint hi0, lo0, hi1, lo1;
            split2(v00, v01, hi0, lo0);
            split2(v10, v11, hi1, lo1);
            *(uint*)(hh + (size_t)m * 512 + n)       = hi0;
            *(uint*)(hl + (size_t)m * 512 + n)       = lo0;
            *(uint*)(hh + (size_t)(m + 8) * 512 + n) = hi1;
            *(uint*)(hl + (size_t)(m + 8) * 512 + n) = lo1;
        }
    }
    #pragma unroll
    for (int j = 0; j < 4; ++j) {
        float s0 = sqa[j][0], s1 = sqa[j][1];
        #pragma unroll
        for (int o = 16; o >= 4; o >>= 1) {
            s0 += __shfl_xor_sync(0xffffffffu, s0, o);
            s1 += __shfl_xor_sync(0xffffffffu, s1, o);
        }
        if (L < 4) {
            int n = n0 + wn * 32 + j * 8 + L * 2;
            atomicAdd(&g_gsq[bloc * CH + n], s0);
            atomicAdd(&g_gsq[bloc * CH + n + 1], s1);
        }
    }
}

// ---------------- K4: GRN scale + bias2 ----------------
__global__ void grn_prep_kernel(const float* __restrict__ grn_g, const float* __restrict__ grn_b,
                                const float* __restrict__ w2, const float* __restrict__ b2) {
    if (blockIdx.x == 0) {
        __shared__ float red[512];
        int e = threadIdx.x;
        for (int b = 0; b < BATCH; ++b) {
            float g = sqrtf(g_gsq[b * CH + e]);
            red[e] = g;
            __syncthreads();
            for (int o = 256; o > 0; o >>= 1) {
                if (e < o) red[e] += red[e + o];
                __syncthreads();
            }
            float mean = red[0] * (1.f / 512.f);
            __syncthreads();
            float nx = g / (mean + 1e-6f);
            g_s[b * CH + e] = 1.f + grn_g[e] * nx;
        }
    } else {
        int c = threadIdx.x;
        if (c < C_) {
            float a = b2[c];
            for (int e = 0; e < CH; ++e) a += grn_b[e] * w2[e * C_ + c];
            g_bias2[c] = a;
        }
    }
}

// ---------------- K4b: scaled w2 -> transposed split bf16 planes [b][c][e] ----------------
__global__ void w2cvt_kernel(const float* __restrict__ w2) {
    int id = blockIdx.x * 512 + threadIdx.x;       // 65536 elems
    int e = id >> 7, c = id & 127;                 // w2[e][c]
    float w = w2[id];
    #pragma unroll
    for (int b = 0; b < BATCH; ++b) {
        float v = g_s[b * CH + e] * w;
        __nv_bfloat16 h = __float2bfloat16_rn(v);
        float rem = v - __bfloat162float(h);
        g_w2h[(size_t)b * 65536 + c * 512 + e] = __bfloat16_as_ushort(h);
        g_w2l[(size_t)b * 65536 + c * 512 + e] = __bfloat16_as_ushort(__float2bfloat16_rn(rem));
    }
}

// ---------------- K5: GEMM2 (HMMA split-bf16) + bias2 + residual -> NCDHW ----------------
// grid (NPANEL), 256 threads, smem 66048
__global__ void __launch_bounds__(256) gemm2_mma(const float* __restrict__ xin,
                                                 float* __restrict__ out) {
    const int tid = threadIdx.x;
    const int bx = blockIdx.x;
    const int bloc = (bx >= PPB) ? 1 : 0;
    const uint32_t smb = smem_u32(smraw);

    const int r = tid >> 1, cc = tid & 1;
    const int csw = (cc ^ ((r >> 2) & 1)) & 1;
    const uint32_t sdst0 = smb + (uint32_t)(r * 32 + csw * 16);
    const char* gAh = (const char*)(g_hh + (size_t)bx * 65536 + (size_t)r * 512 + cc * 8);
    const char* gAl = (const char*)(g_hl + (size_t)bx * 65536 + (size_t)r * 512 + cc * 8);
    const char* gBh = (const char*)(g_w2h + (size_t)bloc * 65536 + (size_t)r * 512 + cc * 8);
    const char* gBl = (const char*)(g_w2l + (size_t)bloc * 65536 + (size_t)r * 512 + cc * 8);

    const int L = tid & 31, wid = tid >> 5, wm = wid & 1, wn = wid >> 1;
    const int ar = wm * 64 + ((L & 7) | (((L >> 3) & 1) << 3));
    const int asw = (((L >> 4) & 1) ^ ((ar >> 2) & 1)) & 1;
    const int br = wn * 32 + ((L & 7) | (((L >> 4) & 1) << 3));
    const int bsw = (((L >> 3) & 1) ^ ((br >> 2) & 1)) & 1;

    float acc[4][4][4];
    #pragma unroll
    for (int i = 0; i < 4; ++i)
        #pragma unroll
        for (int j = 0; j < 4; ++j)
            #pragma unroll
            for (int k = 0; k < 4; ++k) acc[i][j][k] = 0.f;

    const int NK = 32;  // K=512
    gemm_load_stage(sdst0, gAh, gAl, gBh, gBl);
    for (int s = 0; s < NK; ++s) {
        if (s + 1 < NK) {
            gemm_load_stage(sdst0 + (uint32_t)((s + 1) & 1) * 16384u,
                            gAh + (s + 1) * 32, gAl + (s + 1) * 32,
                            gBh + (s + 1) * 32, gBl + (s + 1) * 32);
            CP_WAIT1();
        } else CP_WAIT0();
        __syncthreads();
        gemm_compute_stage(smb + (uint32_t)(s & 1) * 16384u, ar, asw, br, bsw, acc);
        __syncthreads();
    }

    // epilogue: stage C[m][c] in smem (pad 129), then coalesced NCDHW write with residual
    float* Cs = (float*)smraw;
    #pragma unroll
    for (int i = 0; i < 4; ++i) {
        const int m = wm * 64 + i * 16 + (L >> 2);
        #pragma unroll
        for (int j = 0; j < 4; ++j) {
            const int c = wn * 32 + j * 8 + (L & 3) * 2;
            Cs[m * 129 + c]           = acc[i][j][0];
            Cs[m * 129 + c + 1]       = acc[i][j][1];
            Cs[(m + 8) * 129 + c]     = acc[i][j][2];
            Cs[(m + 8) * 129 + c + 1] = acc[i][j][3];
        }
    }
    __syncthreads();
    const int p0 = (bx - bloc * PPB) * 128;
    for (int t = 0; t < 64; ++t) {
        int idx = tid + 256 * t;
        int p = idx & 127, c = idx >> 7;
        size_t gi = ((size_t)(bloc * C_ + c)) * S_ + p0 + p;
        out[gi] = xin[gi] + Cs[p * 129 + c] + g_bias2[c];
    }
}

// ---------------- launch ----------------
extern "C" void kernel_launch(void* const* d_in, const int* in_sizes, int n_in,
                              void* d_out, int out_size) {
    (void)in_sizes; (void)n_in; (void)out_size;
    const float* x     = (const float*)d_in[0];
    const float* dw_w  = (const float*)d_in[1];
    const float* dw_b  = (const float*)d_in[2];
    const float* ln_g  = (const float*)d_in[3];
    const float* ln_b  = (const float*)d_in[4];
    const float* w1    = (const float*)d_in[5];
    const float* b1    = (const float*)d_in[6];
    const float* grn_g = (const float*)d_in[7];
    const float* grn_b = (const float*)d_in[8];
    const float* w2    = (const float*)d_in[9];
    const float* b2    = (const float*)d_in[10];
    float* out = (float*)d_out;

    const int conv_smem = (7 * 2916 + 343 + 2304) * 4;   // 92236
    const int g1_smem = 32768;
    const int g2_smem = 128 * 129 * 4;                   // 66048 (>= 32768 stage area)
    cudaFuncSetAttribute(conv_dw_kernel, cudaFuncAttributeMaxDynamicSharedMemorySize, conv_smem);
    cudaFuncSetAttribute(gemm2_mma, cudaFuncAttributeMaxDynamicSharedMemorySize, g2_smem);

    zero_gsq_kernel<<<1, 1024>>>();
    w1cvt_kernel<<<128, 512>>>(w1);
    conv_dw_kernel<<<dim3(4, C_, BATCH), 192, conv_smem>>>(x, dw_w);
    trans_ln_kernel<<<dim3(S_ / 32, BATCH), 256>>>(dw_b, ln_g, ln_b);
    gemm1_mma<<<dim3(4, NPANEL), 256, g1_smem>>>(b1);
    grn_prep_kernel<<<2, 512>>>(grn_g, grn_b, w2, b2);
    w2cvt_kernel<<<128, 512>>>(w2);
    gemm2_mma<<<NPANEL, 256, g2_smem>>>(x, out);
}

// round 5
// speedup vs baseline: 1.5476x; 1.1189x over previous
#include <cuda_runtime.h>
#include <cuda_bf16.h>
#include <math.h>
#include <stdint.h>

#define C_     128
#define BATCH  2
#define S_     110592          // 48*48*48
#define NPTS   221184
#define CH     512
#define NPANEL 1728            // NPTS/128
#define PPB    864             // panels per batch

typedef unsigned int uint;
typedef unsigned short ushort;

// single extern shared decl shared by all kernels
extern __shared__ __align__(128) unsigned char smraw[];

// ---------------- scratch ----------------
__device__ float  g_yconv[(size_t)BATCH * C_ * S_];     // conv out NCDHW
__device__ ushort g_ylnh[(size_t)NPTS * C_];            // LN out hi bf16, [panel][m][k]
__device__ ushort g_ylnl[(size_t)NPTS * C_];            // LN out lo
__device__ ushort g_hh  [(size_t)NPTS * CH];            // gelu out hi, [panel][m][e]
__device__ ushort g_hl  [(size_t)NPTS * CH];            // gelu out lo
__device__ ushort g_w1h [CH * C_];                      // w1^T hi: [e][c]
__device__ ushort g_w1l [CH * C_];
__device__ ushort g_w2h [BATCH * C_ * CH];              // scaled w2^T hi: [b][c][e]
__device__ ushort g_w2l [BATCH * C_ * CH];
__device__ float  g_gsq [BATCH * CH];
__device__ float  g_s   [BATCH * CH];
__device__ float  g_bias2[C_];

// ---------------- PTX helpers ----------------
__device__ __forceinline__ uint32_t smem_u32(const void* p) {
    uint32_t a;
    asm("{ .reg .u64 t; cvta.to.shared.u64 t, %1; cvt.u32.u64 %0, t; }" : "=r"(a) : "l"(p));
    return a;
}
#define CP_ASYNC(dst, src) asm volatile("cp.async.cg.shared.global [%0], [%1], 16;" :: "r"(dst), "l"(src))
#define CP_COMMIT()        asm volatile("cp.async.commit_group;")
#define CP_WAIT1()         asm volatile("cp.async.wait_group 1;")
#define CP_WAIT0()         asm volatile("cp.async.wait_group 0;")

__device__ __forceinline__ void ldsm4(uint* r, uint32_t addr) {
    asm volatile("ldmatrix.sync.aligned.m8n8.x4.shared.b16 {%0,%1,%2,%3}, [%4];"
        : "=r"(r[0]), "=r"(r[1]), "=r"(r[2]), "=r"(r[3]) : "r"(addr));
}
__device__ __forceinline__ void mma_bf16(float* c, const uint* a, uint b0, uint b1) {
    asm volatile("mma.sync.aligned.m16n8k16.row.col.f32.bf16.bf16.f32 "
        "{%0,%1,%2,%3}, {%4,%5,%6,%7}, {%8,%9}, {%0,%1,%2,%3};"
        : "+f"(c[0]), "+f"(c[1]), "+f"(c[2]), "+f"(c[3])
        : "r"(a[0]), "r"(a[1]), "r"(a[2]), "r"(a[3]), "r"(b0), "r"(b1));
}
__device__ __forceinline__ void split2(float a, float b, uint& hi, uint& lo) {
    __nv_bfloat16 ah = __float2bfloat16_rn(a), bh = __float2bfloat16_rn(b);
    float ar = a - __bfloat162float(ah), br = b - __bfloat162float(bh);
    __nv_bfloat16 al = __float2bfloat16_rn(ar), bl = __float2bfloat16_rn(br);
    hi = ((uint)__bfloat16_as_ushort(bh) << 16) | (uint)__bfloat16_as_ushort(ah);
    lo = ((uint)__bfloat16_as_ushort(bl) << 16) | (uint)__bfloat16_as_ushort(al);
}
__device__ __forceinline__ float gelu_f(float v) {
    return 0.5f * v * (1.0f + erff(v * 0.70710678118654752f));
}

// per 16-k sub-stage layout (16KB): planes Ah@0, Al@4096, Bh@8192, Bl@12288
// each plane: 128 rows x 16 bf16 (32B/row, two 16B chunks), chunk swizzle: phys_c = c ^ ((r>>2)&1)

__device__ __forceinline__ void gemm_load_sub(uint32_t sdst,
    const char* gAh, const char* gAl, const char* gBh, const char* gBl) {
    CP_ASYNC(sdst         , gAh);
    CP_ASYNC(sdst +  4096u, gAl);
    CP_ASYNC(sdst +  8192u, gBh);
    CP_ASYNC(sdst + 12288u, gBl);
}

__device__ __forceinline__ void gemm_compute_sub(uint32_t sa,
    int ar, int asw, int br, int bsw, float acc[4][4][4]) {
    uint aH[4][4], aL[4][4], bH[2][4], bL[2][4];
    uint32_t abase = sa + (uint32_t)(ar * 32 + asw * 16);
    #pragma unroll
    for (int i = 0; i < 4; ++i) ldsm4(aH[i], abase + i * 512u);
    #pragma unroll
    for (int i = 0; i < 4; ++i) ldsm4(aL[i], abase + 4096u + i * 512u);
    uint32_t bbase = sa + 8192u + (uint32_t)(br * 32 + bsw * 16);
    #pragma unroll
    for (int j = 0; j < 2; ++j) ldsm4(bH[j], bbase + j * 512u);
    #pragma unroll
    for (int j = 0; j < 2; ++j) ldsm4(bL[j], bbase + 4096u + j * 512u);
    #pragma unroll
    for (int i = 0; i < 4; ++i)
        #pragma unroll
        for (int j = 0; j < 4; ++j) {
            uint h0 = bH[j >> 1][(j & 1) * 2], h1 = bH[j >> 1][(j & 1) * 2 + 1];
            uint l0 = bL[j >> 1][(j & 1) * 2], l1 = bL[j >> 1][(j & 1) * 2 + 1];
            mma_bf16(acc[i][j], aH[i], h0, h1);
            mma_bf16(acc[i][j], aH[i], l0, l1);
            mma_bf16(acc[i][j], aL[i], h0, h1);
        }
}

// macro-stage = 2 sub-stages (K=32), one commit group; buffers 32KB each
__device__ __forceinline__ void gemm_load_macro(uint32_t bufbase,
    const char* gAh, const char* gAl, const char* gBh, const char* gBl, int ms) {
    gemm_load_sub(bufbase,          gAh + (2 * ms) * 32,     gAl + (2 * ms) * 32,
                                    gBh + (2 * ms) * 32,     gBl + (2 * ms) * 32);
    gemm_load_sub(bufbase + 16384u, gAh + (2 * ms + 1) * 32, gAl + (2 * ms + 1) * 32,
                                    gBh + (2 * ms + 1) * 32, gBl + (2 * ms + 1) * 32);
    CP_COMMIT();
}

// ---------------- K0: zero gsq ----------------
__global__ void zero_gsq_kernel() {
    int i = threadIdx.x;
    if (i < BATCH * CH) g_gsq[i] = 0.f;
}

// ---------------- K1: depthwise 7x7x7 conv ----------------
__global__ void conv_dw_kernel(const float* __restrict__ x, const float* __restrict__ dw_w) {
    float* sm = (float*)smraw;
    float* planes = sm;
    float* wsm    = sm + 7 * 2916;
    float* outsm  = wsm + 343;

    const int tid = threadIdx.x;
    const int dstart = blockIdx.x * 12;
    const int c = blockIdx.y;
    const int b = blockIdx.z;
    const size_t xbase = ((size_t)(b * C_ + c)) * S_;

    for (int i = tid; i < 343; i += 192) wsm[i] = dw_w[c * 343 + i];

    for (int pl = 0; pl < 7; ++pl) {
        int din = dstart - 3 + pl;
        int slot = ((din % 7) + 7) % 7;
        float* dst = planes + slot * 2916;
        if (din < 0 || din >= 48) {
            for (int i = tid; i < 2916; i += 192) dst[i] = 0.f;
        } else {
            const float* src = x + xbase + (size_t)din * 2304;
            for (int i = tid; i < 2916; i += 192) {
                int hh = i / 54 - 3, ww = i % 54 - 3;
                dst[i] = (hh >= 0 && hh < 48 && ww >= 0 && ww < 48) ? src[hh * 48 + ww] : 0.f;
            }
        }
    }

    const int tx = tid & 7, ty = tid >> 3;
    const int w0 = tx * 6, h0 = ty * 2;

    for (int d = dstart; d < dstart + 12; ++d) {
        __syncthreads();
        float acc[2][6];
        #pragma unroll
        for (int r = 0; r < 2; ++r)
            #pragma unroll
            for (int j = 0; j < 6; ++j) acc[r][j] = 0.f;

        #pragma unroll 1
        for (int dd = 0; dd < 7; ++dd) {
            const float* pl = planes + (((d - 3 + dd) % 7 + 7) % 7) * 2916;
            #pragma unroll
            for (int dh = 0; dh < 7; ++dh) {
                float wv[7];
                #pragma unroll
                for (int k = 0; k < 7; ++k) wv[k] = wsm[dd * 49 + dh * 7 + k];
                #pragma unroll
                for (int r = 0; r < 2; ++r) {
                    const float* row = pl + (h0 + r + dh) * 54 + w0;
                    float xr[12];
                    #pragma unroll
                    for (int q = 0; q < 12; ++q) xr[q] = row[q];
                    #pragma unroll
                    for (int j = 0; j < 6; ++j)
                        #pragma unroll
                        for (int k = 0; k < 7; ++k)
                            acc[r][j] = fmaf(xr[j + k], wv[k], acc[r][j]);
                }
            }
        }
        #pragma unroll
        for (int r = 0; r < 2; ++r)
            #pragma unroll
            for (int j = 0; j < 6; ++j)
                outsm[(h0 + r) * 48 + w0 + j] = acc[r][j];
        __syncthreads();
        float* dst = g_yconv + xbase + (size_t)d * 2304;
        for (int i = tid; i < 2304; i += 192) dst[i] = outsm[i];
        if (d + 1 < dstart + 12) {
            int din = d + 4;
            int slot = ((din % 7) + 7) % 7;
            float* dstp = planes + slot * 2916;
            if (din >= 48) {
                for (int i = tid; i < 2916; i += 192) dstp[i] = 0.f;
            } else {
                const float* src = x + xbase + (size_t)din * 2304;
                for (int i = tid; i < 2916; i += 192) {
                    int hh = i / 54 - 3, ww = i % 54 - 3;
                    dstp[i] = (hh >= 0 && hh < 48 && ww >= 0 && ww < 48) ? src[hh * 48 + ww] : 0.f;
                }
            }
        }
    }
}

// ---------------- K2: transpose + dw_b + LN -> split bf16 [panel][m][k] ----------------
__global__ void trans_ln_kernel(const float* __restrict__ dwb,
                                const float* __restrict__ lng,
                                const float* __restrict__ lnb) {
    __shared__ float tile[C_ * 33];
    __shared__ float ps[256], pq[256], musm[32], rssm[32];
    const int tid = threadIdx.x;
    const int tx = tid & 31, ty = tid >> 5;
    const int p0 = blockIdx.x * 32;
    const int b = blockIdx.y;

    for (int g = 0; g < 16; ++g) {
        int c = ty * 16 + g;
        tile[c * 33 + tx] = g_yconv[((size_t)(b * C_ + c)) * S_ + p0 + tx] + dwb[c];
    }
    __syncthreads();
    float s = 0.f, q = 0.f;
    for (int g = 0; g < 16; ++g) {
        float v = tile[(ty * 16 + g) * 33 + tx];
        s += v; q += v * v;
    }
    ps[ty * 32 + tx] = s; pq[ty * 32 + tx] = q;
    __syncthreads();
    if (ty == 0) {
        float S1 = 0.f, Q1 = 0.f;
        for (int u = 0; u < 8; ++u) { S1 += ps[u * 32 + tx]; Q1 += pq[u * 32 + tx]; }
        float mu = S1 * (1.f / 128.f);
        float var = Q1 * (1.f / 128.f) - mu * mu;
        musm[tx] = mu;
        rssm[tx] = rsqrtf(var + 1e-6f);
    }
    __syncthreads();
    size_t panel = ((size_t)b * S_ + p0) >> 7;
    int mo = (int)(((size_t)b * S_ + p0) & 127);
    ushort* dh = g_ylnh + panel * 16384;
    ushort* dl = g_ylnl + panel * 16384;
    for (int t = 0; t < 16; ++t) {
        int idx = tid + 256 * t;
        int c = idx & 127, pp = idx >> 7;           // pp 0..31
        float v = (tile[c * 33 + pp] - musm[pp]) * rssm[pp] * lng[c] + lnb[c];
        __nv_bfloat16 h = __float2bfloat16_rn(v);
        float rem = v - __bfloat162float(h);
        dh[(mo + pp) * 128 + c] = __bfloat16_as_ushort(h);
        dl[(mo + pp) * 128 + c] = __bfloat16_as_ushort(__float2bfloat16_rn(rem));
    }
}

// ---------------- K2b: w1 -> transposed split bf16 planes [e][c] ----------------
__global__ void w1cvt_kernel(const float* __restrict__ w1) {
    int id = blockIdx.x * 512 + threadIdx.x;       // 65536 elems
    int cc = id >> 9, e = id & 511;                // w1[cc][e]
    float v = w1[id];
    __nv_bfloat16 h = __float2bfloat16_rn(v);
    float rem = v - __bfloat162float(h);
    g_w1h[e * 128 + cc] = __bfloat16_as_ushort(h);
    g_w1l[e * 128 + cc] = __bfloat16_as_ushort(__float2bfloat16_rn(rem));
}

// ---------------- K3: GEMM1 (HMMA split-bf16) + b1 + GELU -> h planes, + gsq ----------------
// grid (4, NPANEL), 256 threads, smem 65536 (2 macro buffers of 32KB)
__global__ void __launch_bounds__(256) gemm1_mma(const float* __restrict__ b1) {
    const int tid = threadIdx.x;
    const int n0 = blockIdx.x * 128;
    const int bx = blockIdx.y;
    const uint32_t smb = smem_u32(smraw);

    const int r = tid >> 1, cc = tid & 1;
    const int csw = (cc ^ ((r >> 2) & 1)) & 1;
    const uint32_t sdst0 = smb + (uint32_t)(r * 32 + csw * 16);
    const char* gAh = (const char*)(g_ylnh + (size_t)bx * 16384 + r * 128 + cc * 8);
    const char* gAl = (const char*)(g_ylnl + (size_t)bx * 16384 + r * 128 + cc * 8);
    const char* gBh = (const char*)(g_w1h + (size_t)(n0 + r) * 128 + cc * 8);
    const char* gBl = (const char*)(g_w1l + (size_t)(n0 + r) * 128 + cc * 8);

    const int L = tid & 31, wid = tid >> 5, wm = wid & 1, wn = wid >> 1;
    const int ar = wm * 64 + ((L & 7) | (((L >> 3) & 1) << 3));
    const int asw = (((L >> 4) & 1) ^ ((ar >> 2) & 1)) & 1;
    const int br = wn * 32 + ((L & 7) | (((L >> 4) & 1) << 3));
    const int bsw = (((L >> 3) & 1) ^ ((br >> 2) & 1)) & 1;

    float acc[4][4][4];
    #pragma unroll
    for (int i = 0; i < 4; ++i)
        #pragma unroll
        for (int j = 0; j < 4; ++j)
            #pragma unroll
            for (int k = 0; k < 4; ++k) acc[i][j][k] = 0.f;

    const int NM = 4;   // K=128, macro=32
    gemm_load_macro(sdst0, gAh, gAl, gBh, gBl, 0);
    for (int ms = 0; ms < NM; ++ms) {
        if (ms + 1 < NM) {
            gemm_load_macro(sdst0 + (uint32_t)((ms + 1) & 1) * 32768u, gAh, gAl, gBh, gBl, ms + 1);
            CP_WAIT1();
        } else CP_WAIT0();
        __syncthreads();
        uint32_t base = smb + (uint32_t)(ms & 1) * 32768u;
        gemm_compute_sub(base,          ar, asw, br, bsw, acc);
        gemm_compute_sub(base + 16384u, ar, asw, br, bsw, acc);
        __syncthreads();
    }

    // epilogue
    const int bloc = (bx >= PPB) ? 1 : 0;
    ushort* hh = g_hh + (size_t)bx * 65536;
    ushort* hl = g_hl + (size_t)bx * 65536;
    float sqa[4][2];
    #pragma unroll
    for (int j = 0; j < 4; ++j) { sqa[j][0] = 0.f; sqa[j][1] = 0.f; }

    #pragma unroll
    for (int i = 0; i < 4; ++i) {
        const int m = wm * 64 + i * 16 + (L >> 2);
        #pragma unroll
        for (int j = 0; j < 4; ++j) {
            const int n = n0 + wn * 32 + j * 8 + (L & 3) * 2;
            float b10 = __ldg(b1 + n), b11 = __ldg(b1 + n + 1);
            float v00 = gelu_f(acc[i][j][0] + b10);
            float v01 = gelu_f(acc[i][j][1] + b11);
            float v10 = gelu_f(acc[i][j][2] + b10);
            float v11 = gelu_f(acc[i][j][3] + b11);
            sqa[j][0] += v00 * v00 + v10 * v10;
            sqa[j][1] += v01 * v01 + v11 * v11;
            uint hi0, lo0, hi1, lo1;
            split2(v00, v01, hi0, lo0);
            split2(v10, v11, hi1, lo1);
            *(uint*)(hh + (size_t)m * 512 + n)       = hi0;
            *(uint*)(hl + (size_t)m * 512 + n)       = lo0;
            *(uint*)(hh + (size_t)(m + 8) * 512 + n) = hi1;
            *(uint*)(hl + (size_t)(m + 8) * 512 + n) = lo1;
        }
    }
    #pragma unroll
    for (int j = 0; j < 4; ++j) {
        float s0 = sqa[j][0], s1 = sqa[j][1];
        #pragma unroll
        for (int o = 16; o >= 4; o >>= 1) {
            s0 += __shfl_xor_sync(0xffffffffu, s0, o);
            s1 += __shfl_xor_sync(0xffffffffu, s1, o);
        }
        if (L < 4) {
            int n = n0 + wn * 32 + j * 8 + L * 2;
            atomicAdd(&g_gsq[bloc * CH + n], s0);
            atomicAdd(&g_gsq[bloc * CH + n + 1], s1);
        }
    }
}

// ---------------- K4: GRN scale + bias2 ----------------
__global__ void grn_prep_kernel(const float* __restrict__ grn_g, const float* __restrict__ grn_b,
                                const float* __restrict__ w2, const float* __restrict__ b2) {
    if (blockIdx.x == 0) {
        __shared__ float red[512];
        int e = threadIdx.x;
        for (int b = 0; b < BATCH; ++b) {
            float g = sqrtf(g_gsq[b * CH + e]);
            red[e] = g;
            __syncthreads();
            for (int o = 256; o > 0; o >>= 1) {
                if (e < o) red[e] += red[e + o];
                __syncthreads();
            }
            float mean = red[0] * (1.f / 512.f);
            __syncthreads();
            float nx = g / (mean + 1e-6f);
            g_s[b * CH + e] = 1.f + grn_g[e] * nx;
        }
    } else {
        int c = threadIdx.x;
        if (c < C_) {
            float a = b2[c];
            for (int e = 0; e < CH; ++e) a += grn_b[e] * w2[e * C_ + c];
            g_bias2[c] = a;
        }
    }
}

// ---------------- K4b: scaled w2 -> transposed split bf16 planes [b][c][e] ----------------
__global__ void w2cvt_kernel(const float* __restrict__ w2) {
    int id = blockIdx.x * 512 + threadIdx.x;       // 65536 elems
    int e = id >> 7, c = id & 127;                 // w2[e][c]
    float w = w2[id];
    #pragma unroll
    for (int b = 0; b < BATCH; ++b) {
        float v = g_s[b * CH + e] * w;
        __nv_bfloat16 h = __float2bfloat16_rn(v);
        float rem = v - __bfloat162float(h);
        g_w2h[(size_t)b * 65536 + c * 512 + e] = __bfloat16_as_ushort(h);
        g_w2l[(size_t)b * 65536 + c * 512 + e] = __bfloat16_as_ushort(__float2bfloat16_rn(rem));
    }
}

// ---------------- K5: GEMM2 (HMMA split-bf16) + bias2 + residual -> NCDHW ----------------
// grid (NPANEL), 256 threads, smem 66048
__global__ void __launch_bounds__(256) gemm2_mma(const float* __restrict__ xin,
                                                 float* __restrict__ out) {
    const int tid = threadIdx.x;
    const int bx = blockIdx.x;
    const int bloc = (bx >= PPB) ? 1 : 0;
    const uint32_t smb = smem_u32(smraw);

    const int r = tid >> 1, cc = tid & 1;
    const int csw = (cc ^ ((r >> 2) & 1)) & 1;
    const uint32_t sdst0 = smb + (uint32_t)(r * 32 + csw * 16);
    const char* gAh = (const char*)(g_hh + (size_t)bx * 65536 + (size_t)r * 512 + cc * 8);
    const char* gAl = (const char*)(g_hl + (size_t)bx * 65536 + (size_t)r * 512 + cc * 8);
    const char* gBh = (const char*)(g_w2h + (size_t)bloc * 65536 + (size_t)r * 512 + cc * 8);
    const char* gBl = (const char*)(g_w2l + (size_t)bloc * 65536 + (size_t)r * 512 + cc * 8);

    const int L = tid & 31, wid = tid >> 5, wm = wid & 1, wn = wid >> 1;
    const int ar = wm * 64 + ((L & 7) | (((L >> 3) & 1) << 3));
    const int asw = (((L >> 4) & 1) ^ ((ar >> 2) & 1)) & 1;
    const int br = wn * 32 + ((L & 7) | (((L >> 4) & 1) << 3));
    const int bsw = (((L >> 3) & 1) ^ ((br >> 2) & 1)) & 1;

    float acc[4][4][4];
    #pragma unroll
    for (int i = 0; i < 4; ++i)
        #pragma unroll
        for (int j = 0; j < 4; ++j)
            #pragma unroll
            for (int k = 0; k < 4; ++k) acc[i][j][k] = 0.f;

    const int NM = 16;  // K=512, macro=32
    gemm_load_macro(sdst0, gAh, gAl, gBh, gBl, 0);
    for (int ms = 0; ms < NM; ++ms) {
        if (ms + 1 < NM) {
            gemm_load_macro(sdst0 + (uint32_t)((ms + 1) & 1) * 32768u, gAh, gAl, gBh, gBl, ms + 1);
            CP_WAIT1();
        } else CP_WAIT0();
        __syncthreads();
        uint32_t base = smb + (uint32_t)(ms & 1) * 32768u;
        gemm_compute_sub(base,          ar, asw, br, bsw, acc);
        gemm_compute_sub(base + 16384u, ar, asw, br, bsw, acc);
        __syncthreads();
    }

    // epilogue: stage C[m][c] in smem (pad 129), then coalesced NCDHW write with residual
    float* Cs = (float*)smraw;
    #pragma unroll
    for (int i = 0; i < 4; ++i) {
        const int m = wm * 64 + i * 16 + (L >> 2);
        #pragma unroll
        for (int j = 0; j < 4; ++j) {
            const int c = wn * 32 + j * 8 + (L & 3) * 2;
            Cs[m * 129 + c]           = acc[i][j][0];
            Cs[m * 129 + c + 1]       = acc[i][j][1];
            Cs[(m + 8) * 129 + c]     = acc[i][j][2];
            Cs[(m + 8) * 129 + c + 1] = acc[i][j][3];
        }
    }
    __syncthreads();
    const int p0 = (bx - bloc * PPB) * 128;
    for (int t = 0; t < 64; ++t) {
        int idx = tid + 256 * t;
        int p = idx & 127, c = idx >> 7;
        size_t gi = ((size_t)(bloc * C_ + c)) * S_ + p0 + p;
        out[gi] = xin[gi] + Cs[p * 129 + c] + g_bias2[c];
    }
}

// ---------------- launch ----------------
extern "C" void kernel_launch(void* const* d_in, const int* in_sizes, int n_in,
                              void* d_out, int out_size) {
    (void)in_sizes; (void)n_in; (void)out_size;
    const float* x     = (const float*)d_in[0];
    const float* dw_w  = (const float*)d_in[1];
    const float* dw_b  = (const float*)d_in[2];
    const float* ln_g  = (const float*)d_in[3];
    const float* ln_b  = (const float*)d_in[4];
    const float* w1    = (const float*)d_in[5];
    const float* b1    = (const float*)d_in[6];
    const float* grn_g = (const float*)d_in[7];
    const float* grn_b = (const float*)d_in[8];
    const float* w2    = (const float*)d_in[9];
    const float* b2    = (const float*)d_in[10];
    float* out = (float*)d_out;

    const int conv_smem = (7 * 2916 + 343 + 2304) * 4;   // 92236
    const int g1_smem = 65536;
    const int g2_smem = 128 * 129 * 4;                   // 66048 (>= 65536 stage area)
    cudaFuncSetAttribute(conv_dw_kernel, cudaFuncAttributeMaxDynamicSharedMemorySize, conv_smem);
    cudaFuncSetAttribute(gemm1_mma, cudaFuncAttributeMaxDynamicSharedMemorySize, g1_smem);
    cudaFuncSetAttribute(gemm2_mma, cudaFuncAttributeMaxDynamicSharedMemorySize, g2_smem);

    zero_gsq_kernel<<<1, 1024>>>();
    w1cvt_kernel<<<128, 512>>>(w1);
    conv_dw_kernel<<<dim3(4, C_, BATCH), 192, conv_smem>>>(x, dw_w);
    trans_ln_kernel<<<dim3(S_ / 32, BATCH), 256>>>(dw_b, ln_g, ln_b);
    gemm1_mma<<<dim3(4, NPANEL), 256, g1_smem>>>(b1);
    grn_prep_kernel<<<2, 512>>>(grn_g, grn_b, w2, b2);
    w2cvt_kernel<<<128, 512>>>(w2);
    gemm2_mma<<<NPANEL, 256, g2_smem>>>(x, out);
}